// round 12
// baseline (speedup 1.0000x reference)
#include <cuda_runtime.h>
#include <cuda_bf16.h>
#include <math.h>

#define NN 100000
#define EE 1000000
#define GG 5000
#define SLOPEF 0.01f

// ---------------- scratch ----------------
__device__ float g_x[NN*64];
__device__ float g_xl1[NN*64];
__device__ float g_h[NN*64];            // interleaved split-bf16 h: uint2{hi,lo}[NN*32]
__device__ float g_p[NN*64];
__device__ float g_dots[2*NN];          // pai | pan
__device__ float g_pan2[NN];
__device__ float g_accd[NN*64 + NN];    // pacc | pdenom
__device__ float g_gout[GG*64];
__device__ float g_molaccd[GG*64 + GG]; // accG | denG
__device__ float g_gdot[GG];

__device__ __forceinline__ float leaky(float v){ return v > 0.f ? v : SLOPEF * v; }

__device__ __forceinline__ void red4(float* p, float a, float b, float c, float d){
    asm volatile("red.global.add.v4.f32 [%0], {%1,%2,%3,%4};"
                 :: "l"(p), "f"(a), "f"(b), "f"(c), "f"(d) : "memory");
}
__device__ __forceinline__ void red2(float* p, float a, float b){
    asm volatile("red.global.add.v2.f32 [%0], {%1,%2};"
                 :: "l"(p), "f"(a), "f"(b) : "memory");
}
__device__ __forceinline__ unsigned packbf(float x, float y){
    __nv_bfloat162 t = __floats2bfloat162_rn(x, y);
    return *reinterpret_cast<unsigned*>(&t);
}
__device__ __forceinline__ float bfhi(float x){
    return __bfloat162float(__float2bfloat16_rn(x));
}
__device__ __forceinline__ void mma_bf16(float* c, const unsigned* a, unsigned b0, unsigned b1){
    asm volatile("mma.sync.aligned.m16n8k16.row.col.f32.bf16.bf16.f32 "
                 "{%0,%1,%2,%3},{%4,%5,%6,%7},{%8,%9},{%0,%1,%2,%3};"
                 : "+f"(c[0]), "+f"(c[1]), "+f"(c[2]), "+f"(c[3])
                 : "r"(a[0]), "r"(a[1]), "r"(a[2]), "r"(a[3]), "r"(b0), "r"(b1));
}

#define BLDH 100     // GRU B row stride (uint2 units), ≡4 mod 16 -> conflict-free
#define MBU  68      // att/proj B row stride (uint2 units), ≡4 mod 16
#define AHLD 36      // A row stride (uint2 units), ≡4 mod 16

// ================= dual projection (256 thr, uint2-interleaved split) =================
__global__ __launch_bounds__(256)
void k_proj(float* __restrict__ out1, float* __restrict__ out2,
            const float* __restrict__ in,
            const float* __restrict__ W1, const float* __restrict__ b1v,
            const float* __restrict__ W2, const float* __restrict__ b2v,
            const float* __restrict__ dotw, float* __restrict__ dotout, int nrows)
{
    extern __shared__ uint2 smu2[];
    uint2* B1 = smu2;               // 32*MBU
    uint2* B2 = B1 + 32*MBU;
    uint2* Aa = B2 + 32*MBU;        // 64*AHLD
    int tx = threadIdx.x;
    for (int i = tx; i < 2048; i += 256){
        int k2 = i >> 6, n = i & 63;
        float w0 = W1[n*64 + 2*k2], w1 = W1[n*64 + 2*k2 + 1];
        float u0 = W2[n*80 + 2*k2], u1 = W2[n*80 + 2*k2 + 1];
        float w0h = bfhi(w0), w1h = bfhi(w1), u0h = bfhi(u0), u1h = bfhi(u1);
        B1[k2*MBU + n] = make_uint2(packbf(w0, w1), packbf(w0 - w0h, w1 - w1h));
        B2[k2*MBU + n] = make_uint2(packbf(u0, u1), packbf(u0 - u0h, u1 - u1h));
    }
    int wid = tx >> 5, lane = tx & 31;
    int rowgrp = wid >> 1, khalf = wid & 1;
    int qrow = lane >> 2, qk = lane & 3;
    int r0 = rowgrp * 16;
    int ntile = (nrows + 63) >> 6;
    for (int tile = blockIdx.x; tile < ntile; tile += gridDim.x){
        int base = tile << 6;
        __syncthreads();
        for (int i = tx; i < 2048; i += 256){
            int r = i >> 5, k2 = i & 31;
            int row = base + r;
            float2 v = make_float2(0.f, 0.f);
            if (row < nrows) v = *(const float2*)(in + row*64 + 2*k2);
            float vxh = bfhi(v.x), vyh = bfhi(v.y);
            Aa[r*AHLD + k2] = make_uint2(packbf(v.x, v.y), packbf(v.x - vxh, v.y - vyh));
        }
        __syncthreads();
        float ca[4][4], cb[4][4];
        #pragma unroll
        for (int t = 0; t < 4; t++)
            #pragma unroll
            for (int j = 0; j < 4; j++){ ca[t][j] = 0.f; cb[t][j] = 0.f; }
        int ra = (r0 + qrow)*AHLD, rb = (r0 + qrow + 8)*AHLD;
        #pragma unroll
        for (int kt = 0; kt < 4; kt++){
            int pb = kt*8;
            uint2 a0 = Aa[ra+pb+qk], a1 = Aa[rb+pb+qk], a2 = Aa[ra+pb+qk+4], a3 = Aa[rb+pb+qk+4];
            unsigned ah[4] = {a0.x, a1.x, a2.x, a3.x};
            unsigned al[4] = {a0.y, a1.y, a2.y, a3.y};
            #pragma unroll
            for (int t = 0; t < 4; t++){
                int n0 = khalf*32 + t*8 + qrow;
                int o0 = (pb+qk)*MBU + n0, o1 = (pb+4+qk)*MBU + n0;
                uint2 b0 = B1[o0], b1 = B1[o1];
                mma_bf16(ca[t], ah, b0.x, b1.x);
                mma_bf16(ca[t], ah, b0.y, b1.y);
                mma_bf16(ca[t], al, b0.x, b1.x);
                uint2 d0 = B2[o0], d1 = B2[o1];
                mma_bf16(cb[t], ah, d0.x, d1.x);
                mma_bf16(cb[t], ah, d0.y, d1.y);
                mma_bf16(cb[t], al, d0.x, d1.x);
            }
        }
        float pd[2] = {0.f, 0.f};
        #pragma unroll
        for (int t = 0; t < 4; t++){
            int kc0 = khalf*32 + t*8 + 2*qk;
            float a0 = __ldg(b1v+kc0), a1 = __ldg(b1v+kc0+1);
            float e0 = __ldg(b2v+kc0), e1 = __ldg(b2v+kc0+1);
            #pragma unroll
            for (int half = 0; half < 2; half++){
                int grow = base + r0 + qrow + 8*half;
                if (grow < nrows){
                    float v0 = leaky(ca[t][2*half] + a0), v1 = leaky(ca[t][2*half+1] + a1);
                    *(float2*)(out1 + grow*64 + kc0) = make_float2(v0, v1);
                    *(float2*)(out2 + grow*64 + kc0) = make_float2(cb[t][2*half] + e0, cb[t][2*half+1] + e1);
                    pd[half] += v0*__ldg(dotw+kc0) + v1*__ldg(dotw+kc0+1);
                }
            }
        }
        #pragma unroll
        for (int o = 1; o <= 2; o <<= 1){
            pd[0] += __shfl_xor_sync(0xffffffffu, pd[0], o);
            pd[1] += __shfl_xor_sync(0xffffffffu, pd[1], o);
        }
        if (qk == 0){
            #pragma unroll
            for (int half = 0; half < 2; half++){
                int grow = base + r0 + qrow + 8*half;
                if (grow < nrows) atomicAdd(dotout + grow, pd[half]);
            }
        }
    }
}

// ================= attend GEMM (uint2-interleaved): split-bf16 h out; zero acc/den ====
__global__ __launch_bounds__(256)
void k_att(uint2* __restrict__ outu,
           float* __restrict__ acc, float* __restrict__ den,
           const float* __restrict__ W, const float* __restrict__ bias,
           float* __restrict__ z1, float* __restrict__ z2, int nrows)
{
    extern __shared__ uint2 smu2[];
    uint2* Bw = smu2;               // 32*MBU
    uint2* Aa = Bw + 32*MBU;        // 64*AHLD
    float* dens = (float*)(Aa + 64*AHLD);
    int tx = threadIdx.x;
    for (int i = tx; i < 2048; i += 256){
        int k2 = i >> 6, n = i & 63;
        float w0 = W[n*64 + 2*k2], w1 = W[n*64 + 2*k2 + 1];
        float w0h = bfhi(w0), w1h = bfhi(w1);
        Bw[k2*MBU + n] = make_uint2(packbf(w0, w1), packbf(w0 - w0h, w1 - w1h));
    }
    int wid = tx >> 5, lane = tx & 31;
    int rowgrp = wid >> 1, khalf = wid & 1;
    int qrow = lane >> 2, qk = lane & 3;
    int r0 = rowgrp * 16;
    int ntile = (nrows + 63) >> 6;
    for (int tile = blockIdx.x; tile < ntile; tile += gridDim.x){
        int base = tile << 6;
        __syncthreads();
        for (int i = tx; i < 2048; i += 256){
            int r = i >> 5, k2 = i & 31;
            int row = base + r;
            float2 v = make_float2(0.f, 0.f);
            if (row < nrows){
                v = *(const float2*)(acc + row*64 + 2*k2);
                *(float2*)(acc + row*64 + 2*k2) = make_float2(0.f, 0.f);
            }
            float vxh = bfhi(v.x), vyh = bfhi(v.y);
            Aa[r*AHLD + k2] = make_uint2(packbf(v.x, v.y), packbf(v.x - vxh, v.y - vyh));
        }
        if (tx < 64){
            int row = base + tx;
            float dv = 0.f;
            if (row < nrows){
                dv = den[row]; den[row] = 0.f;
                if (z1) z1[row] = 0.f;
                if (z2) z2[row] = 0.f;
            }
            dens[tx] = dv;
        }
        __syncthreads();
        float c[4][4];
        #pragma unroll
        for (int t = 0; t < 4; t++)
            #pragma unroll
            for (int j = 0; j < 4; j++) c[t][j] = 0.f;
        int ra = (r0 + qrow)*AHLD, rb = (r0 + qrow + 8)*AHLD;
        #pragma unroll
        for (int kt = 0; kt < 4; kt++){
            int pb = kt*8;
            uint2 a0 = Aa[ra+pb+qk], a1 = Aa[rb+pb+qk], a2 = Aa[ra+pb+qk+4], a3 = Aa[rb+pb+qk+4];
            unsigned ah[4] = {a0.x, a1.x, a2.x, a3.x};
            unsigned al[4] = {a0.y, a1.y, a2.y, a3.y};
            #pragma unroll
            for (int t = 0; t < 4; t++){
                int n0 = khalf*32 + t*8 + qrow;
                int o0 = (pb+qk)*MBU + n0, o1 = (pb+4+qk)*MBU + n0;
                uint2 b0 = Bw[o0], b1 = Bw[o1];
                mma_bf16(c[t], ah, b0.x, b1.x);
                mma_bf16(c[t], ah, b0.y, b1.y);
                mma_bf16(c[t], al, b0.x, b1.x);
            }
        }
        #pragma unroll
        for (int t = 0; t < 4; t++){
            int kc0 = khalf*32 + t*8 + 2*qk;
            float b0 = __ldg(bias+kc0), b1 = __ldg(bias+kc0+1);
            #pragma unroll
            for (int half = 0; half < 2; half++){
                int grow = base + r0 + qrow + 8*half;
                if (grow < nrows){
                    float dv = dens[r0 + qrow + 8*half];
                    float inv = 1.f / (dv + 1e-16f);
                    float sc = dv * inv;
                    float v0 = c[t][2*half]*inv   + b0*sc;
                    float v1 = c[t][2*half+1]*inv + b1*sc;
                    v0 = v0 > 0.f ? v0 : expm1f(v0);
                    v1 = v1 > 0.f ? v1 : expm1f(v1);
                    float v0h = bfhi(v0), v1h = bfhi(v1);
                    outu[grow*32 + (kc0 >> 1)] =
                        make_uint2(packbf(v0, v1), packbf(v0 - v0h, v1 - v1h));
                }
            }
        }
    }
}

// ================= GRU: uint2-interleaved everywhere; parity N-split, 2 CTAs/SM ======
__global__ __launch_bounds__(256, 2)
void k_gru(float* __restrict__ xout, float* __restrict__ xout2,
           const uint2* __restrict__ hinu,
           const float* __restrict__ xprev,
           const float* __restrict__ wih, const float* __restrict__ whh,
           const float* __restrict__ bih, const float* __restrict__ bhh,
           const float* __restrict__ dotw1, const float* __restrict__ dotw2,
           float* __restrict__ dot1, float* __restrict__ dot2,
           const int* __restrict__ batchv, float* __restrict__ gsum,
           int nrows)
{
    extern __shared__ uint2 smu2[];
    uint2* B1  = smu2;              // 32*BLDH
    uint2* B2  = B1 + 32*BLDH;
    uint2* Ah2 = B2 + 32*BLDH;      // 64*AHLD
    uint2* Ax2 = Ah2 + 64*AHLD;
    int tx = threadIdx.x;
    int hb = blockIdx.x & 1;

    for (int i = tx; i < 32*96; i += 256){
        int k2 = i & 31, nl = i >> 5;
        int ng = (nl >> 5)*64 + hb*32 + (nl & 31);
        float w0 = wih[ng*64 + 2*k2], w1 = wih[ng*64 + 2*k2 + 1];
        float u0 = whh[ng*64 + 2*k2], u1 = whh[ng*64 + 2*k2 + 1];
        float w0h = bfhi(w0), w1h = bfhi(w1), u0h = bfhi(u0), u1h = bfhi(u1);
        B1[k2*BLDH + nl] = make_uint2(packbf(w0, w1), packbf(w0 - w0h, w1 - w1h));
        B2[k2*BLDH + nl] = make_uint2(packbf(u0, u1), packbf(u0 - u0h, u1 - u1h));
    }
    __syncthreads();

    int wid = tx >> 5, lane = tx & 31;
    int rowgrp = wid >> 1, kq = wid & 1;
    int qrow = lane >> 2, qk = lane & 3;
    int r0 = rowgrp*16;
    int ntile = (nrows + 63) / 64;
    int tstep = gridDim.x >> 1;

    for (int tile = blockIdx.x >> 1; tile < ntile; tile += tstep){
        int base = tile * 64;
        for (int i = tx; i < 2048; i += 256){
            int r = i >> 5, k2 = i & 31;
            int row = base + r;
            uint2 hv = make_uint2(0u, 0u);
            float x0 = 0.f, x1 = 0.f;
            if (row < nrows){
                hv = hinu[row*32 + k2];
                float2 xv = *(const float2*)(xprev + row*64 + 2*k2);
                x0 = xv.x; x1 = xv.y;
            }
            float x0h = bfhi(x0), x1h = bfhi(x1);
            Ah2[r*AHLD + k2] = hv;
            Ax2[r*AHLD + k2] = make_uint2(packbf(x0, x1), packbf(x0 - x0h, x1 - x1h));
        }
        __syncthreads();

        float c1[6][4], c2[6][4];
        #pragma unroll
        for (int t = 0; t < 6; t++)
            #pragma unroll
            for (int j = 0; j < 4; j++){ c1[t][j] = 0.f; c2[t][j] = 0.f; }

        int ra = (r0 + qrow)*AHLD, rb = (r0 + qrow + 8)*AHLD;
        #pragma unroll
        for (int kt = 0; kt < 4; kt++){
            int pb = kt*8;
            uint2 h0 = Ah2[ra+pb+qk], h1 = Ah2[rb+pb+qk], h2 = Ah2[ra+pb+qk+4], h3 = Ah2[rb+pb+qk+4];
            uint2 x0 = Ax2[ra+pb+qk], x1 = Ax2[rb+pb+qk], x2 = Ax2[ra+pb+qk+4], x3 = Ax2[rb+pb+qk+4];
            unsigned ahh[4] = {h0.x, h1.x, h2.x, h3.x};
            unsigned ahl[4] = {h0.y, h1.y, h2.y, h3.y};
            unsigned axh[4] = {x0.x, x1.x, x2.x, x3.x};
            unsigned axl[4] = {x0.y, x1.y, x2.y, x3.y};
            #pragma unroll
            for (int t = 0; t < 6; t++){
                int g = t >> 1, i = t & 1;
                int n0 = g*32 + kq*16 + i*8 + qrow;
                int o0 = (pb+qk)*BLDH + n0, o1 = (pb+4+qk)*BLDH + n0;
                uint2 b0 = B1[o0], b1 = B1[o1];
                mma_bf16(c1[t], ahh, b0.x, b1.x);
                mma_bf16(c1[t], ahh, b0.y, b1.y);
                mma_bf16(c1[t], ahl, b0.x, b1.x);
                uint2 d0 = B2[o0], d1 = B2[o1];
                mma_bf16(c2[t], axh, d0.x, d1.x);
                mma_bf16(c2[t], axh, d0.y, d1.y);
                mma_bf16(c2[t], axl, d0.x, d1.x);
            }
        }

        float pd1[2] = {0.f, 0.f}, pd2[2] = {0.f, 0.f};
        #pragma unroll
        for (int half = 0; half < 2; half++){
            int grow = base + r0 + qrow + 8*half;
            if (grow < nrows){
                int gseg = batchv ? __ldg(batchv + grow) : 0;
                #pragma unroll
                for (int i = 0; i < 2; i++){
                    int kc0 = hb*32 + kq*16 + i*8 + 2*qk;
                    float2 xp = *(const float2*)(xprev + grow*64 + kc0);
                    float v[2];
                    #pragma unroll
                    for (int cc = 0; cc < 2; cc++){
                        int kc = kc0 + cc, ci = half*2 + cc;
                        float sr = c1[i][ci]   + c2[i][ci]   + __ldg(bih+kc)     + __ldg(bhh+kc);
                        float sz = c1[2+i][ci] + c2[2+i][ci] + __ldg(bih+64+kc) + __ldg(bhh+64+kc);
                        float hn = c2[4+i][ci] + __ldg(bhh+128+kc);
                        float rr = 1.f/(1.f + expf(-sr));
                        float zz = 1.f/(1.f + expf(-sz));
                        float nn = tanhf(c1[4+i][ci] + __ldg(bih+128+kc) + rr*hn);
                        float xv = cc ? xp.y : xp.x;
                        v[cc] = fmaxf((1.f - zz)*nn + zz*xv, 0.f);
                    }
                    float2 o = make_float2(v[0], v[1]);
                    *(float2*)(xout + grow*64 + kc0) = o;
                    if (xout2) *(float2*)(xout2 + grow*64 + kc0) = o;
                    if (dotw1) pd1[half] += o.x*__ldg(dotw1+kc0) + o.y*__ldg(dotw1+kc0+1);
                    if (dotw2) pd2[half] += o.x*__ldg(dotw2+kc0) + o.y*__ldg(dotw2+kc0+1);
                    if (gsum) red2(gsum + gseg*64 + kc0, o.x, o.y);
                }
            }
        }
        if (dotw1){
            #pragma unroll
            for (int o = 1; o <= 2; o <<= 1){
                pd1[0] += __shfl_xor_sync(0xffffffffu, pd1[0], o);
                pd1[1] += __shfl_xor_sync(0xffffffffu, pd1[1], o);
                pd2[0] += __shfl_xor_sync(0xffffffffu, pd2[0], o);
                pd2[1] += __shfl_xor_sync(0xffffffffu, pd2[1], o);
            }
            if (qk == 0){
                #pragma unroll
                for (int half = 0; half < 2; half++){
                    int grow = base + r0 + qrow + 8*half;
                    if (grow < nrows){
                        atomicAdd(dot1 + grow, pd1[half]);
                        if (dotw2) atomicAdd(dot2 + grow, pd2[half]);
                    }
                }
            }
        }
        __syncthreads();
    }
}

// ---------------- GATEConv edge pass: half-warp per edge ----------------
__global__ void k_gate_edge(const int* __restrict__ ei, const float* __restrict__ eattr,
                            const float* __restrict__ p, const float* __restrict__ si,
                            const float* __restrict__ gate_nl_w,
                            const float* __restrict__ align_w,
                            const float* __restrict__ align_b,
                            float* __restrict__ accb, float* __restrict__ denom)
{
    __shared__ float sw[16][64];
    int tx = threadIdx.x, lane = tx & 31;
    for (int i = tx; i < 1024; i += 256){
        int d = i >> 6, k = i & 63;
        sw[d][k] = gate_nl_w[k*80 + 64 + d];
    }
    __syncthreads();
    int sub = lane >> 4, l4 = lane & 15;
    float4 aj4 = *(const float4*)(align_w + 64 + l4*4);
    float ab = __ldg(align_b);
    int sbase = sub << 4;
    int wid = (blockIdx.x*blockDim.x + tx) >> 5;
    int nw  = (gridDim.x*blockDim.x) >> 5;
    for (int q = wid*4; q < EE; q += nw*4){
        int e0 = q + sub*2, e1 = e0 + 1;
        int s0 = ei[e0], t0 = ei[EE+e0];
        int s1 = ei[e1], t1 = ei[EE+e1];
        float ea0 = eattr[e0*16 + l4];
        float ea1 = eattr[e1*16 + l4];
        float4 x0 = *(const float4*)(p + s0*64 + l4*4);
        float4 x1 = *(const float4*)(p + s1*64 + l4*4);
        float si0 = __ldg(si + t0), si1 = __ldg(si + t1);
        #pragma unroll
        for (int d = 0; d < 16; d++){
            float4 w4 = *(const float4*)&sw[d][l4*4];
            float e0d = __shfl_sync(0xffffffffu, ea0, sbase + d);
            float e1d = __shfl_sync(0xffffffffu, ea1, sbase + d);
            x0.x += e0d*w4.x; x0.y += e0d*w4.y; x0.z += e0d*w4.z; x0.w += e0d*w4.w;
            x1.x += e1d*w4.x; x1.y += e1d*w4.y; x1.z += e1d*w4.z; x1.w += e1d*w4.w;
        }
        x0.x = leaky(x0.x); x0.y = leaky(x0.y); x0.z = leaky(x0.z); x0.w = leaky(x0.w);
        x1.x = leaky(x1.x); x1.y = leaky(x1.y); x1.z = leaky(x1.z); x1.w = leaky(x1.w);
        float p0 = x0.x*aj4.x + x0.y*aj4.y + x0.z*aj4.z + x0.w*aj4.w;
        float p1 = x1.x*aj4.x + x1.y*aj4.y + x1.z*aj4.z + x1.w*aj4.w;
        #pragma unroll
        for (int o = 8; o > 0; o >>= 1){
            p0 += __shfl_xor_sync(0xffffffffu, p0, o);
            p1 += __shfl_xor_sync(0xffffffffu, p1, o);
        }
        float ec0 = expf(leaky(si0 + p0 + ab));
        float ec1 = expf(leaky(si1 + p1 + ab));
        if (l4 == 0){
            atomicAdd(denom + t0, ec0);
            atomicAdd(denom + t1, ec1);
        }
        red4(accb + t0*64 + l4*4, ec0*x0.x, ec0*x0.y, ec0*x0.z, ec0*x0.w);
        red4(accb + t1*64 + l4*4, ec1*x1.x, ec1*x1.y, ec1*x1.z, ec1*x1.w);
    }
}

// ---------------- GATConv fused edge pass ----------------
__global__ void k_conv_edge(const int* __restrict__ ei, const float* __restrict__ x,
                            const float* __restrict__ ai, const float* __restrict__ an,
                            const float* __restrict__ bptr,
                            float* __restrict__ accb, float* __restrict__ denom)
{
    float b = __ldg(bptr);
    int tx = threadIdx.x, lane = tx & 31;
    int sub = lane >> 4, l4 = lane & 15;
    int wid = (blockIdx.x*blockDim.x + tx) >> 5;
    int nw  = (gridDim.x*blockDim.x) >> 5;
    for (int q = wid*4; q < EE; q += nw*4){
        int e0 = q + sub*2, e1 = e0 + 1;
        int s0 = ei[e0], t0 = ei[EE+e0];
        int s1 = ei[e1], t1 = ei[EE+e1];
        float a0 = __ldg(ai+t0), n0 = __ldg(an+s0);
        float a1 = __ldg(ai+t1), n1 = __ldg(an+s1);
        float4 v0 = *(const float4*)(x + s0*64 + l4*4);
        float4 v1 = *(const float4*)(x + s1*64 + l4*4);
        float ec0 = expf(leaky(a0 + n0 + b));
        float ec1 = expf(leaky(a1 + n1 + b));
        red4(accb + t0*64 + l4*4, ec0*v0.x, ec0*v0.y, ec0*v0.z, ec0*v0.w);
        red4(accb + t1*64 + l4*4, ec1*v1.x, ec1*v1.y, ec1*v1.z, ec1*v1.w);
        if (l4 == 0){
            atomicAdd(denom + t0, ec0);
            atomicAdd(denom + t1, ec1);
        }
    }
}

// ---------------- molecule node->graph pass (optionally fused mix + inline dot) --------
__global__ void k_mol_edge(const int* __restrict__ batch, const float* __restrict__ xv,
                           const float* __restrict__ mixb,
                           const float* __restrict__ gdot, const float* __restrict__ ndot,
                           const float* __restrict__ ajw, const float* __restrict__ bptr,
                           float* __restrict__ accG, float* __restrict__ denG)
{
    float b = __ldg(bptr);
    int tx = threadIdx.x, lane = tx & 31;
    int sub = lane >> 4, l4 = lane & 15;
    float4 aj4 = make_float4(0.f, 0.f, 0.f, 0.f);
    if (ajw) aj4 = *(const float4*)(ajw + l4*4);
    int wid = (blockIdx.x*blockDim.x + tx) >> 5;
    int nw  = (gridDim.x*blockDim.x) >> 5;
    for (int pair = wid; pair < NN/2; pair += nw){
        int n = pair*2 + sub;
        int g = batch[n];
        float4 m = *(const float4*)(xv + n*64 + l4*4);
        float nd;
        if (mixb){
            float4 w = *(const float4*)(mixb + n*64 + l4*4);
            m.x = 0.5f*(m.x + w.x); m.y = 0.5f*(m.y + w.y);
            m.z = 0.5f*(m.z + w.z); m.w = 0.5f*(m.w + w.w);
            nd = m.x*aj4.x + m.y*aj4.y + m.z*aj4.z + m.w*aj4.w;
            #pragma unroll
            for (int o = 8; o > 0; o >>= 1) nd += __shfl_xor_sync(0xffffffffu, nd, o);
        } else {
            nd = __ldg(ndot + n);
        }
        float ec = expf(leaky(gdot[g] + nd + b));
        red4(accG + g*64 + l4*4, ec*m.x, ec*m.y, ec*m.z, ec*m.w);
        if (l4 == 0) atomicAdd(denG + g, ec);
    }
}

// ---------------- per-row dot, optional in-place relu ----------------
__global__ void k_dotg(float* __restrict__ o1, const float* __restrict__ w1,
                       float* __restrict__ in, int nrows, int dorelu)
{
    int wid  = (blockIdx.x*blockDim.x + threadIdx.x) >> 5;
    int lane = threadIdx.x & 31;
    int nw   = (gridDim.x*blockDim.x) >> 5;
    for (int r = wid; r < nrows; r += nw){
        float v1 = in[r*64 + lane], v2 = in[r*64 + lane + 32];
        if (dorelu){
            v1 = fmaxf(v1, 0.f); v2 = fmaxf(v2, 0.f);
            in[r*64 + lane] = v1; in[r*64 + lane + 32] = v2;
        }
        float s = v1*__ldg(w1+lane) + v2*__ldg(w1+lane+32);
        #pragma unroll
        for (int o = 16; o > 0; o >>= 1) s += __shfl_xor_sync(0xffffffffu, s, o);
        if (lane == 0) o1[r] = s;
    }
}

__global__ void k_final(const float* __restrict__ gout, const float* __restrict__ w,
                        const float* __restrict__ b, float* __restrict__ out, int n)
{
    int wid  = (blockIdx.x*blockDim.x + threadIdx.x) >> 5;
    int lane = threadIdx.x & 31;
    if (wid >= n) return;
    float s = gout[wid*64 + lane]*__ldg(w + lane) + gout[wid*64 + lane + 32]*__ldg(w + lane + 32);
    #pragma unroll
    for (int o = 16; o > 0; o >>= 1) s += __shfl_xor_sync(0xffffffffu, s, o);
    if (lane == 0) out[wid] = s + __ldg(b);
}

// =====================================================================
extern "C" void kernel_launch(void* const* d_in, const int* in_sizes, int n_in,
                              void* d_out_, int out_size)
{
    const float* raw           = (const float*)d_in[0];
    const int*   ei            = (const int*)  d_in[1];
    const float* eattr         = (const float*)d_in[2];
    const int*   batch         = (const int*)  d_in[3];
    const float* lin1_w        = (const float*)d_in[4];
    const float* lin1_b        = (const float*)d_in[5];
    const float* gate_nl_w     = (const float*)d_in[6];
    const float* gate_nl_b     = (const float*)d_in[7];
    const float* gate_align_w  = (const float*)d_in[8];
    const float* gate_align_b  = (const float*)d_in[9];
    const float* gate_attend_w = (const float*)d_in[10];
    const float* gate_attend_b = (const float*)d_in[11];
    const float* conv_align_w  = (const float*)d_in[12];
    const float* conv_align_b  = (const float*)d_in[13];
    const float* conv_attend_w = (const float*)d_in[14];
    const float* conv_attend_b = (const float*)d_in[15];
    const float* agru_wih      = (const float*)d_in[16];
    const float* agru_whh      = (const float*)d_in[17];
    const float* agru_bih      = (const float*)d_in[18];
    const float* agru_bhh      = (const float*)d_in[19];
    const float* mol_align_w   = (const float*)d_in[20];
    const float* mol_align_b   = (const float*)d_in[21];
    const float* mol_attend_w  = (const float*)d_in[22];
    const float* mol_attend_b  = (const float*)d_in[23];
    const float* mgru_wih      = (const float*)d_in[24];
    const float* mgru_whh      = (const float*)d_in[25];
    const float* mgru_bih      = (const float*)d_in[26];
    const float* mgru_bhh      = (const float*)d_in[27];
    const float* lin2_w        = (const float*)d_in[28];
    const float* lin2_b        = (const float*)d_in[29];
    float* outp = (float*)d_out_;

    float *px, *pxl1, *ph, *pp, *pdots, *ppan2, *paccd, *pgout, *pmol, *pgdot;
    cudaGetSymbolAddress((void**)&px,     g_x);
    cudaGetSymbolAddress((void**)&pxl1,   g_xl1);
    cudaGetSymbolAddress((void**)&ph,     g_h);
    cudaGetSymbolAddress((void**)&pp,     g_p);
    cudaGetSymbolAddress((void**)&pdots,  g_dots);
    cudaGetSymbolAddress((void**)&ppan2,  g_pan2);
    cudaGetSymbolAddress((void**)&paccd,  g_accd);
    cudaGetSymbolAddress((void**)&pgout,  g_gout);
    cudaGetSymbolAddress((void**)&pmol,   g_molaccd);
    cudaGetSymbolAddress((void**)&pgdot,  g_gdot);

    float* pai    = pdots;
    float* pan    = pdots + NN;
    float* pacc   = paccd;
    float* pdenom = paccd + NN*64;
    float* paccG  = pmol;
    float* pdenG  = pmol + GG*64;
    uint2* phu = (uint2*)ph;
    uint2* ppu = (uint2*)pp;

    const int GRU_SMEM  = (2*32*BLDH + 2*64*AHLD) * 8;     // 88064
    const int PROJ_SMEM = (2*32*MBU + 64*AHLD) * 8;        // 53248
    const int ATT_SMEM  = (32*MBU + 64*AHLD) * 8 + 256;    // 36096
    cudaFuncSetAttribute(k_gru,  cudaFuncAttributeMaxDynamicSharedMemorySize, GRU_SMEM);
    cudaFuncSetAttribute(k_proj, cudaFuncAttributeMaxDynamicSharedMemorySize, PROJ_SMEM);
    cudaFuncSetAttribute(k_att,  cudaFuncAttributeMaxDynamicSharedMemorySize, ATT_SMEM);

    const int NT = (NN + 63) / 64;
    const int GT = (GG + 63) / 64;
    const int PG  = NT < 592 ? NT : 592;
    const int AG  = NT < 592 ? NT : 592;
    const int GRG  = 296;
    const int GRGG = 2*GT < 296 ? 2*GT : 296;

    // ---- initial zeroing ----
    cudaMemsetAsync(pdots, 0, 2*NN*sizeof(float));
    cudaMemsetAsync(paccd, 0, (NN*64 + NN)*sizeof(float));
    cudaMemsetAsync(pgout, 0, GG*64*sizeof(float));
    cudaMemsetAsync(pmol,  0, (GG*64 + GG)*sizeof(float));

    // ---- dual projection ----
    k_proj<<<PG, 256, PROJ_SMEM>>>(px, pp, raw, lin1_w, lin1_b, gate_nl_w, gate_nl_b,
                                   gate_align_w, pai, NN);

    // ---- GATEConv ----
    k_gate_edge<<<2048, 256>>>(ei, eattr, pp, pai, gate_nl_w, gate_align_w, gate_align_b,
                               pacc, pdenom);
    k_att<<<AG, 256, ATT_SMEM>>>(phu, pacc, pdenom, gate_attend_w, gate_attend_b,
                                 pai, pan, NN);
    k_gru<<<GRG, 256, GRU_SMEM>>>(px, nullptr, phu, px,
                                  agru_wih, agru_whh, agru_bih, agru_bhh,
                                  conv_align_w, conv_align_w + 64, pai, pan,
                                  nullptr, nullptr, NN);

    // ---- GATConv l = 0 ----
    k_conv_edge<<<2048, 256>>>(ei, px, pai, pan, conv_align_b, pacc, pdenom);
    k_att<<<AG, 256, ATT_SMEM>>>(phu, pacc, pdenom, conv_attend_w, conv_attend_b,
                                 pai, pan, NN);
    k_gru<<<GRG, 256, GRU_SMEM>>>(px, pxl1, phu, px,
                                  agru_wih + 192*64, agru_whh + 192*64,
                                  agru_bih + 192,    agru_bhh + 192,
                                  conv_align_w + 128, conv_align_w + 192, pai, pan,
                                  nullptr, nullptr, NN);

    // ---- GATConv l = 1 ----
    k_conv_edge<<<2048, 256>>>(ei, px, pai, pan, conv_align_b + 1, pacc, pdenom);
    k_att<<<AG, 256, ATT_SMEM>>>(phu, pacc, pdenom, conv_attend_w + 4096, conv_attend_b + 64,
                                 ppan2, nullptr, NN);
    k_gru<<<GRG, 256, GRU_SMEM>>>(px, nullptr, phu, px,
                                  agru_wih + 2*192*64, agru_whh + 2*192*64,
                                  agru_bih + 2*192,    agru_bhh + 2*192,
                                  mol_align_w + 64, nullptr, ppan2, nullptr,
                                  batch, pgout, NN);

    // ---- molecule readout ----
    k_dotg<<<128, 256>>>(pgdot, mol_align_w, pgout, GG, 1);

    // t = 0: mixed = 0.5*(x + xl1), fused in mol_edge
    k_mol_edge<<<512, 256>>>(batch, px, pxl1, pgdot, nullptr,
                             mol_align_w + 64, mol_align_b, paccG, pdenG);
    k_att<<<GT, 256, ATT_SMEM>>>(ppu, paccG, pdenG, mol_attend_w, mol_attend_b,
                                 nullptr, nullptr, GG);
    k_gru<<<GRGG, 256, GRU_SMEM>>>(pgout, nullptr, ppu, pgout,
                                   mgru_wih, mgru_whh, mgru_bih, mgru_bhh,
                                   nullptr, nullptr, nullptr, nullptr,
                                   nullptr, nullptr, GG);

    // t = 1: mixed == x; ndot = ppan2
    k_dotg<<<128, 256>>>(pgdot, mol_align_w, pgout, GG, 0);
    k_mol_edge<<<512, 256>>>(batch, px, nullptr, pgdot, ppan2,
                             nullptr, mol_align_b, paccG, pdenG);
    k_att<<<GT, 256, ATT_SMEM>>>(ppu, paccG, pdenG, mol_attend_w, mol_attend_b,
                                 nullptr, nullptr, GG);
    k_gru<<<GRGG, 256, GRU_SMEM>>>(pgout, nullptr, ppu, pgout,
                                   mgru_wih, mgru_whh, mgru_bih, mgru_bhh,
                                   nullptr, nullptr, nullptr, nullptr,
                                   nullptr, nullptr, GG);

    k_final<<<(GG*32 + 255)/256, 256>>>(pgout, lin2_w, lin2_b, outp, GG);
}

// round 13
// speedup vs baseline: 1.0666x; 1.0666x over previous
#include <cuda_runtime.h>
#include <cuda_bf16.h>
#include <math.h>

#define NN 100000
#define EE 1000000
#define GG 5000
#define SLOPEF 0.01f

// ---------------- scratch ----------------
__device__ float g_x[NN*64];
__device__ float g_xl1[NN*64];
__device__ float g_h[NN*64];            // interleaved split-bf16 h: uint2{hi,lo}[NN*32]
__device__ float g_p[NN*64];
__device__ float g_dots[2*NN];          // pai | pan
__device__ float g_pan2[NN];
__device__ float g_accd[NN*64 + NN];    // pacc | pdenom
__device__ float g_gout[GG*64];
__device__ float g_molaccd[GG*64 + GG]; // accG | denG
__device__ float g_gdot[GG];

__device__ __forceinline__ float leaky(float v){ return v > 0.f ? v : SLOPEF * v; }

__device__ __forceinline__ void red4(float* p, float a, float b, float c, float d){
    asm volatile("red.global.add.v4.f32 [%0], {%1,%2,%3,%4};"
                 :: "l"(p), "f"(a), "f"(b), "f"(c), "f"(d) : "memory");
}
__device__ __forceinline__ void red2(float* p, float a, float b){
    asm volatile("red.global.add.v2.f32 [%0], {%1,%2};"
                 :: "l"(p), "f"(a), "f"(b) : "memory");
}
__device__ __forceinline__ unsigned packbf(float x, float y){
    __nv_bfloat162 t = __floats2bfloat162_rn(x, y);
    return *reinterpret_cast<unsigned*>(&t);
}
__device__ __forceinline__ float bfhi(float x){
    return __bfloat162float(__float2bfloat16_rn(x));
}
__device__ __forceinline__ void mma_bf16(float* c, const unsigned* a, unsigned b0, unsigned b1){
    asm volatile("mma.sync.aligned.m16n8k16.row.col.f32.bf16.bf16.f32 "
                 "{%0,%1,%2,%3},{%4,%5,%6,%7},{%8,%9},{%0,%1,%2,%3};"
                 : "+f"(c[0]), "+f"(c[1]), "+f"(c[2]), "+f"(c[3])
                 : "r"(a[0]), "r"(a[1]), "r"(a[2]), "r"(a[3]), "r"(b0), "r"(b1));
}

#define BLDH 104
#define MB 72
#define AHLD 36

// ================= dual projection (256 thr) =================
__global__ __launch_bounds__(256)
void k_proj(float* __restrict__ out1, float* __restrict__ out2,
            const float* __restrict__ in,
            const float* __restrict__ W1, const float* __restrict__ b1v,
            const float* __restrict__ W2, const float* __restrict__ b2v,
            const float* __restrict__ dotw, float* __restrict__ dotout, int nrows)
{
    extern __shared__ unsigned smu[];
    unsigned* B1h = smu;
    unsigned* B1l = B1h + 32*MB;
    unsigned* B2h = B1l + 32*MB;
    unsigned* B2l = B2h + 32*MB;
    unsigned* Ah  = B2l + 32*MB;
    unsigned* Al  = Ah + 64*AHLD;
    int tx = threadIdx.x;
    for (int i = tx; i < 2048; i += 256){
        int k2 = i >> 6, n = i & 63;
        float w0 = W1[n*64 + 2*k2], w1 = W1[n*64 + 2*k2 + 1];
        float u0 = W2[n*80 + 2*k2], u1 = W2[n*80 + 2*k2 + 1];
        float w0h = bfhi(w0), w1h = bfhi(w1), u0h = bfhi(u0), u1h = bfhi(u1);
        B1h[k2*MB + n] = packbf(w0, w1);
        B1l[k2*MB + n] = packbf(w0 - w0h, w1 - w1h);
        B2h[k2*MB + n] = packbf(u0, u1);
        B2l[k2*MB + n] = packbf(u0 - u0h, u1 - u1h);
    }
    int wid = tx >> 5, lane = tx & 31;
    int rowgrp = wid >> 1, khalf = wid & 1;
    int qrow = lane >> 2, qk = lane & 3;
    int r0 = rowgrp * 16;
    int ntile = (nrows + 63) >> 6;
    for (int tile = blockIdx.x; tile < ntile; tile += gridDim.x){
        int base = tile << 6;
        __syncthreads();
        for (int i = tx; i < 2048; i += 256){
            int r = i >> 5, k2 = i & 31;
            int row = base + r;
            float2 v = make_float2(0.f, 0.f);
            if (row < nrows) v = *(const float2*)(in + row*64 + 2*k2);
            float vxh = bfhi(v.x), vyh = bfhi(v.y);
            Ah[r*AHLD + k2] = packbf(v.x, v.y);
            Al[r*AHLD + k2] = packbf(v.x - vxh, v.y - vyh);
        }
        __syncthreads();
        float ca[4][4], cb[4][4];
        #pragma unroll
        for (int t = 0; t < 4; t++)
            #pragma unroll
            for (int j = 0; j < 4; j++){ ca[t][j] = 0.f; cb[t][j] = 0.f; }
        int ra = (r0 + qrow)*AHLD, rb = (r0 + qrow + 8)*AHLD;
        #pragma unroll
        for (int kt = 0; kt < 4; kt++){
            int pb = kt*8;
            unsigned ah[4], al[4];
            ah[0]=Ah[ra+pb+qk]; ah[1]=Ah[rb+pb+qk]; ah[2]=Ah[ra+pb+qk+4]; ah[3]=Ah[rb+pb+qk+4];
            al[0]=Al[ra+pb+qk]; al[1]=Al[rb+pb+qk]; al[2]=Al[ra+pb+qk+4]; al[3]=Al[rb+pb+qk+4];
            #pragma unroll
            for (int t = 0; t < 4; t++){
                int n0 = khalf*32 + t*8 + qrow;
                int o0 = (pb+qk)*MB + n0, o1 = (pb+4+qk)*MB + n0;
                unsigned b0 = B1h[o0], b1 = B1h[o1];
                mma_bf16(ca[t], ah, b0, b1);
                mma_bf16(ca[t], ah, B1l[o0], B1l[o1]);
                mma_bf16(ca[t], al, b0, b1);
                unsigned d0 = B2h[o0], d1 = B2h[o1];
                mma_bf16(cb[t], ah, d0, d1);
                mma_bf16(cb[t], ah, B2l[o0], B2l[o1]);
                mma_bf16(cb[t], al, d0, d1);
            }
        }
        float pd[2] = {0.f, 0.f};
        #pragma unroll
        for (int t = 0; t < 4; t++){
            int kc0 = khalf*32 + t*8 + 2*qk;
            float a0 = __ldg(b1v+kc0), a1 = __ldg(b1v+kc0+1);
            float e0 = __ldg(b2v+kc0), e1 = __ldg(b2v+kc0+1);
            #pragma unroll
            for (int half = 0; half < 2; half++){
                int grow = base + r0 + qrow + 8*half;
                if (grow < nrows){
                    float v0 = leaky(ca[t][2*half] + a0), v1 = leaky(ca[t][2*half+1] + a1);
                    *(float2*)(out1 + grow*64 + kc0) = make_float2(v0, v1);
                    *(float2*)(out2 + grow*64 + kc0) = make_float2(cb[t][2*half] + e0, cb[t][2*half+1] + e1);
                    pd[half] += v0*__ldg(dotw+kc0) + v1*__ldg(dotw+kc0+1);
                }
            }
        }
        #pragma unroll
        for (int o = 1; o <= 2; o <<= 1){
            pd[0] += __shfl_xor_sync(0xffffffffu, pd[0], o);
            pd[1] += __shfl_xor_sync(0xffffffffu, pd[1], o);
        }
        if (qk == 0){
            #pragma unroll
            for (int half = 0; half < 2; half++){
                int grow = base + r0 + qrow + 8*half;
                if (grow < nrows) atomicAdd(dotout + grow, pd[half]);
            }
        }
    }
}

// ================= attend GEMM: writes interleaved split-bf16 h; zeroes acc/den ====
__global__ __launch_bounds__(256)
void k_att(uint2* __restrict__ outu,
           float* __restrict__ acc, float* __restrict__ den,
           const float* __restrict__ W, const float* __restrict__ bias,
           float* __restrict__ z1, float* __restrict__ z2, int nrows)
{
    extern __shared__ unsigned smu[];
    unsigned* Bh = smu;
    unsigned* Bl = Bh + 32*MB;
    unsigned* Ah = Bl + 32*MB;
    unsigned* Al = Ah + 64*AHLD;
    float* dens  = (float*)(Al + 64*AHLD);
    int tx = threadIdx.x;
    for (int i = tx; i < 2048; i += 256){
        int k2 = i >> 6, n = i & 63;
        float w0 = W[n*64 + 2*k2], w1 = W[n*64 + 2*k2 + 1];
        float w0h = bfhi(w0), w1h = bfhi(w1);
        Bh[k2*MB + n] = packbf(w0, w1);
        Bl[k2*MB + n] = packbf(w0 - w0h, w1 - w1h);
    }
    int wid = tx >> 5, lane = tx & 31;
    int rowgrp = wid >> 1, khalf = wid & 1;
    int qrow = lane >> 2, qk = lane & 3;
    int r0 = rowgrp * 16;
    int ntile = (nrows + 63) >> 6;
    for (int tile = blockIdx.x; tile < ntile; tile += gridDim.x){
        int base = tile << 6;
        __syncthreads();
        for (int i = tx; i < 2048; i += 256){
            int r = i >> 5, k2 = i & 31;
            int row = base + r;
            float2 v = make_float2(0.f, 0.f);
            if (row < nrows){
                v = *(const float2*)(acc + row*64 + 2*k2);
                *(float2*)(acc + row*64 + 2*k2) = make_float2(0.f, 0.f);
            }
            float vxh = bfhi(v.x), vyh = bfhi(v.y);
            Ah[r*AHLD + k2] = packbf(v.x, v.y);
            Al[r*AHLD + k2] = packbf(v.x - vxh, v.y - vyh);
        }
        if (tx < 64){
            int row = base + tx;
            float dv = 0.f;
            if (row < nrows){
                dv = den[row]; den[row] = 0.f;
                if (z1) z1[row] = 0.f;
                if (z2) z2[row] = 0.f;
            }
            dens[tx] = dv;
        }
        __syncthreads();
        float c[4][4];
        #pragma unroll
        for (int t = 0; t < 4; t++)
            #pragma unroll
            for (int j = 0; j < 4; j++) c[t][j] = 0.f;
        int ra = (r0 + qrow)*AHLD, rb = (r0 + qrow + 8)*AHLD;
        #pragma unroll
        for (int kt = 0; kt < 4; kt++){
            int pb = kt*8;
            unsigned ah[4], al[4];
            ah[0]=Ah[ra+pb+qk]; ah[1]=Ah[rb+pb+qk]; ah[2]=Ah[ra+pb+qk+4]; ah[3]=Ah[rb+pb+qk+4];
            al[0]=Al[ra+pb+qk]; al[1]=Al[rb+pb+qk]; al[2]=Al[ra+pb+qk+4]; al[3]=Al[rb+pb+qk+4];
            #pragma unroll
            for (int t = 0; t < 4; t++){
                int n0 = khalf*32 + t*8 + qrow;
                int o0 = (pb+qk)*MB + n0, o1 = (pb+4+qk)*MB + n0;
                unsigned b0 = Bh[o0], b1 = Bh[o1];
                mma_bf16(c[t], ah, b0, b1);
                mma_bf16(c[t], ah, Bl[o0], Bl[o1]);
                mma_bf16(c[t], al, b0, b1);
            }
        }
        #pragma unroll
        for (int t = 0; t < 4; t++){
            int kc0 = khalf*32 + t*8 + 2*qk;
            float b0 = __ldg(bias+kc0), b1 = __ldg(bias+kc0+1);
            #pragma unroll
            for (int half = 0; half < 2; half++){
                int grow = base + r0 + qrow + 8*half;
                if (grow < nrows){
                    float dv = dens[r0 + qrow + 8*half];
                    float inv = 1.f / (dv + 1e-16f);
                    float sc = dv * inv;
                    float v0 = c[t][2*half]*inv   + b0*sc;
                    float v1 = c[t][2*half+1]*inv + b1*sc;
                    v0 = v0 > 0.f ? v0 : expm1f(v0);
                    v1 = v1 > 0.f ? v1 : expm1f(v1);
                    float v0h = bfhi(v0), v1h = bfhi(v1);
                    outu[grow*32 + (kc0 >> 1)] =
                        make_uint2(packbf(v0, v1), packbf(v0 - v0h, v1 - v1h));
                }
            }
        }
    }
}

// ================= GRU: interleaved split-bf16 h input; parity N-split, 2 CTAs/SM ======
__global__ __launch_bounds__(256, 2)
void k_gru(float* __restrict__ xout, float* __restrict__ xout2,
           const uint2* __restrict__ hinu,
           const float* __restrict__ xprev,
           const float* __restrict__ wih, const float* __restrict__ whh,
           const float* __restrict__ bih, const float* __restrict__ bhh,
           const float* __restrict__ dotw1, const float* __restrict__ dotw2,
           float* __restrict__ dot1, float* __restrict__ dot2,
           const int* __restrict__ batchv, float* __restrict__ gsum,
           int nrows)
{
    extern __shared__ unsigned smu[];
    unsigned* B1h = smu;
    unsigned* B1l = B1h + 32*BLDH;
    unsigned* B2h = B1l + 32*BLDH;
    unsigned* B2l = B2h + 32*BLDH;
    unsigned* Ahh = B2l + 32*BLDH;
    unsigned* Ahl = Ahh + 64*AHLD;
    unsigned* Axh = Ahl + 64*AHLD;
    unsigned* Axl = Axh + 64*AHLD;
    float* bsm = (float*)(Axl + 64*AHLD);   // [0:64) r-sum, [64:128) z-sum, [128:192) bih_n, [192:256) bhh_n
    int tx = threadIdx.x;
    int hb = blockIdx.x & 1;

    for (int i = tx; i < 32*96; i += 256){
        int k2 = i & 31, nl = i >> 5;
        int ng = (nl >> 5)*64 + hb*32 + (nl & 31);
        float w0 = wih[ng*64 + 2*k2], w1 = wih[ng*64 + 2*k2 + 1];
        float u0 = whh[ng*64 + 2*k2], u1 = whh[ng*64 + 2*k2 + 1];
        float w0h = bfhi(w0), w1h = bfhi(w1), u0h = bfhi(u0), u1h = bfhi(u1);
        B1h[k2*BLDH + nl] = packbf(w0, w1);
        B1l[k2*BLDH + nl] = packbf(w0 - w0h, w1 - w1h);
        B2h[k2*BLDH + nl] = packbf(u0, u1);
        B2l[k2*BLDH + nl] = packbf(u0 - u0h, u1 - u1h);
    }
    if (tx < 64){
        bsm[tx]       = bih[tx]      + bhh[tx];
        bsm[64 + tx]  = bih[64 + tx] + bhh[64 + tx];
        bsm[128 + tx] = bih[128 + tx];
        bsm[192 + tx] = bhh[128 + tx];
    }
    __syncthreads();

    int wid = tx >> 5, lane = tx & 31;
    int rowgrp = wid >> 1, kq = wid & 1;
    int qrow = lane >> 2, qk = lane & 3;
    int r0 = rowgrp*16;
    int ntile = (nrows + 63) / 64;
    int tstep = gridDim.x >> 1;

    for (int tile = blockIdx.x >> 1; tile < ntile; tile += tstep){
        int base = tile * 64;
        for (int i = tx; i < 2048; i += 256){
            int r = i >> 5, k2 = i & 31;
            int row = base + r;
            uint2 hv = make_uint2(0u, 0u);
            float x0 = 0.f, x1 = 0.f;
            if (row < nrows){
                hv = hinu[row*32 + k2];
                float2 xv = *(const float2*)(xprev + row*64 + 2*k2);
                x0 = xv.x; x1 = xv.y;
            }
            float x0h = bfhi(x0), x1h = bfhi(x1);
            Ahh[r*AHLD + k2] = hv.x;
            Ahl[r*AHLD + k2] = hv.y;
            Axh[r*AHLD + k2] = packbf(x0, x1);
            Axl[r*AHLD + k2] = packbf(x0 - x0h, x1 - x1h);
        }
        __syncthreads();

        float c1[6][4], c2[6][4];
        #pragma unroll
        for (int t = 0; t < 6; t++)
            #pragma unroll
            for (int j = 0; j < 4; j++){ c1[t][j] = 0.f; c2[t][j] = 0.f; }

        int ra = (r0 + qrow)*AHLD, rb = (r0 + qrow + 8)*AHLD;
        #pragma unroll
        for (int kt = 0; kt < 4; kt++){
            int pb = kt*8;
            unsigned ahh[4], ahl[4], axh[4], axl[4];
            ahh[0]=Ahh[ra+pb+qk]; ahh[1]=Ahh[rb+pb+qk]; ahh[2]=Ahh[ra+pb+qk+4]; ahh[3]=Ahh[rb+pb+qk+4];
            ahl[0]=Ahl[ra+pb+qk]; ahl[1]=Ahl[rb+pb+qk]; ahl[2]=Ahl[ra+pb+qk+4]; ahl[3]=Ahl[rb+pb+qk+4];
            axh[0]=Axh[ra+pb+qk]; axh[1]=Axh[rb+pb+qk]; axh[2]=Axh[ra+pb+qk+4]; axh[3]=Axh[rb+pb+qk+4];
            axl[0]=Axl[ra+pb+qk]; axl[1]=Axl[rb+pb+qk]; axl[2]=Axl[ra+pb+qk+4]; axl[3]=Axl[rb+pb+qk+4];
            #pragma unroll
            for (int t = 0; t < 6; t++){
                int g = t >> 1, i = t & 1;
                int n0 = g*32 + kq*16 + i*8 + qrow;
                int o0 = (pb+qk)*BLDH + n0, o1 = (pb+4+qk)*BLDH + n0;
                unsigned b0h = B1h[o0], b1h = B1h[o1];
                mma_bf16(c1[t], ahh, b0h, b1h);
                mma_bf16(c1[t], ahh, B1l[o0], B1l[o1]);
                mma_bf16(c1[t], ahl, b0h, b1h);
                unsigned d0h = B2h[o0], d1h = B2h[o1];
                mma_bf16(c2[t], axh, d0h, d1h);
                mma_bf16(c2[t], axh, B2l[o0], B2l[o1]);
                mma_bf16(c2[t], axl, d0h, d1h);
            }
        }

        float pd1[2] = {0.f, 0.f}, pd2[2] = {0.f, 0.f};
        #pragma unroll
        for (int half = 0; half < 2; half++){
            int grow = base + r0 + qrow + 8*half;
            if (grow < nrows){
                int gseg = batchv ? __ldg(batchv + grow) : 0;
                #pragma unroll
                for (int i = 0; i < 2; i++){
                    int kc0 = hb*32 + kq*16 + i*8 + 2*qk;
                    float2 xp = *(const float2*)(xprev + grow*64 + kc0);
                    float v[2];
                    #pragma unroll
                    for (int cc = 0; cc < 2; cc++){
                        int kc = kc0 + cc, ci = half*2 + cc;
                        float sr = c1[i][ci]   + c2[i][ci]   + bsm[kc];
                        float sz = c1[2+i][ci] + c2[2+i][ci] + bsm[64 + kc];
                        float hn = c2[4+i][ci] + bsm[192 + kc];
                        float rr = 1.f/(1.f + expf(-sr));
                        float zz = 1.f/(1.f + expf(-sz));
                        float nn = tanhf(c1[4+i][ci] + bsm[128 + kc] + rr*hn);
                        float xv = cc ? xp.y : xp.x;
                        v[cc] = fmaxf((1.f - zz)*nn + zz*xv, 0.f);
                    }
                    float2 o = make_float2(v[0], v[1]);
                    *(float2*)(xout + grow*64 + kc0) = o;
                    if (xout2) *(float2*)(xout2 + grow*64 + kc0) = o;
                    if (dotw1) pd1[half] += o.x*__ldg(dotw1+kc0) + o.y*__ldg(dotw1+kc0+1);
                    if (dotw2) pd2[half] += o.x*__ldg(dotw2+kc0) + o.y*__ldg(dotw2+kc0+1);
                    if (gsum) red2(gsum + gseg*64 + kc0, o.x, o.y);
                }
            }
        }
        if (dotw1){
            #pragma unroll
            for (int o = 1; o <= 2; o <<= 1){
                pd1[0] += __shfl_xor_sync(0xffffffffu, pd1[0], o);
                pd1[1] += __shfl_xor_sync(0xffffffffu, pd1[1], o);
                pd2[0] += __shfl_xor_sync(0xffffffffu, pd2[0], o);
                pd2[1] += __shfl_xor_sync(0xffffffffu, pd2[1], o);
            }
            if (qk == 0){
                #pragma unroll
                for (int half = 0; half < 2; half++){
                    int grow = base + r0 + qrow + 8*half;
                    if (grow < nrows){
                        atomicAdd(dot1 + grow, pd1[half]);
                        if (dotw2) atomicAdd(dot2 + grow, pd2[half]);
                    }
                }
            }
        }
        __syncthreads();
    }
}

// ---------------- GATEConv edge pass: half-warp per edge ----------------
__global__ void k_gate_edge(const int* __restrict__ ei, const float* __restrict__ eattr,
                            const float* __restrict__ p, const float* __restrict__ si,
                            const float* __restrict__ gate_nl_w,
                            const float* __restrict__ align_w,
                            const float* __restrict__ align_b,
                            float* __restrict__ accb, float* __restrict__ denom)
{
    __shared__ float sw[16][64];
    int tx = threadIdx.x, lane = tx & 31;
    for (int i = tx; i < 1024; i += 256){
        int d = i >> 6, k = i & 63;
        sw[d][k] = gate_nl_w[k*80 + 64 + d];
    }
    __syncthreads();
    int sub = lane >> 4, l4 = lane & 15;
    float4 aj4 = *(const float4*)(align_w + 64 + l4*4);
    float ab = __ldg(align_b);
    int sbase = sub << 4;
    int wid = (blockIdx.x*blockDim.x + tx) >> 5;
    int nw  = (gridDim.x*blockDim.x) >> 5;
    for (int q = wid*4; q < EE; q += nw*4){
        int e0 = q + sub*2, e1 = e0 + 1;
        int s0 = ei[e0], t0 = ei[EE+e0];
        int s1 = ei[e1], t1 = ei[EE+e1];
        float ea0 = eattr[e0*16 + l4];
        float ea1 = eattr[e1*16 + l4];
        float4 x0 = *(const float4*)(p + s0*64 + l4*4);
        float4 x1 = *(const float4*)(p + s1*64 + l4*4);
        float si0 = __ldg(si + t0), si1 = __ldg(si + t1);
        #pragma unroll
        for (int d = 0; d < 16; d++){
            float4 w4 = *(const float4*)&sw[d][l4*4];
            float e0d = __shfl_sync(0xffffffffu, ea0, sbase + d);
            float e1d = __shfl_sync(0xffffffffu, ea1, sbase + d);
            x0.x += e0d*w4.x; x0.y += e0d*w4.y; x0.z += e0d*w4.z; x0.w += e0d*w4.w;
            x1.x += e1d*w4.x; x1.y += e1d*w4.y; x1.z += e1d*w4.z; x1.w += e1d*w4.w;
        }
        x0.x = leaky(x0.x); x0.y = leaky(x0.y); x0.z = leaky(x0.z); x0.w = leaky(x0.w);
        x1.x = leaky(x1.x); x1.y = leaky(x1.y); x1.z = leaky(x1.z); x1.w = leaky(x1.w);
        float p0 = x0.x*aj4.x + x0.y*aj4.y + x0.z*aj4.z + x0.w*aj4.w;
        float p1 = x1.x*aj4.x + x1.y*aj4.y + x1.z*aj4.z + x1.w*aj4.w;
        #pragma unroll
        for (int o = 8; o > 0; o >>= 1){
            p0 += __shfl_xor_sync(0xffffffffu, p0, o);
            p1 += __shfl_xor_sync(0xffffffffu, p1, o);
        }
        float ec0 = expf(leaky(si0 + p0 + ab));
        float ec1 = expf(leaky(si1 + p1 + ab));
        if (l4 == 0){
            atomicAdd(denom + t0, ec0);
            atomicAdd(denom + t1, ec1);
        }
        red4(accb + t0*64 + l4*4, ec0*x0.x, ec0*x0.y, ec0*x0.z, ec0*x0.w);
        red4(accb + t1*64 + l4*4, ec1*x1.x, ec1*x1.y, ec1*x1.z, ec1*x1.w);
    }
}

// ---------------- GATConv fused edge pass ----------------
__global__ void k_conv_edge(const int* __restrict__ ei, const float* __restrict__ x,
                            const float* __restrict__ ai, const float* __restrict__ an,
                            const float* __restrict__ bptr,
                            float* __restrict__ accb, float* __restrict__ denom)
{
    float b = __ldg(bptr);
    int tx = threadIdx.x, lane = tx & 31;
    int sub = lane >> 4, l4 = lane & 15;
    int wid = (blockIdx.x*blockDim.x + tx) >> 5;
    int nw  = (gridDim.x*blockDim.x) >> 5;
    for (int q = wid*4; q < EE; q += nw*4){
        int e0 = q + sub*2, e1 = e0 + 1;
        int s0 = ei[e0], t0 = ei[EE+e0];
        int s1 = ei[e1], t1 = ei[EE+e1];
        float a0 = __ldg(ai+t0), n0 = __ldg(an+s0);
        float a1 = __ldg(ai+t1), n1 = __ldg(an+s1);
        float4 v0 = *(const float4*)(x + s0*64 + l4*4);
        float4 v1 = *(const float4*)(x + s1*64 + l4*4);
        float ec0 = expf(leaky(a0 + n0 + b));
        float ec1 = expf(leaky(a1 + n1 + b));
        red4(accb + t0*64 + l4*4, ec0*v0.x, ec0*v0.y, ec0*v0.z, ec0*v0.w);
        red4(accb + t1*64 + l4*4, ec1*v1.x, ec1*v1.y, ec1*v1.z, ec1*v1.w);
        if (l4 == 0){
            atomicAdd(denom + t0, ec0);
            atomicAdd(denom + t1, ec1);
        }
    }
}

// ---------------- molecule node->graph pass (optionally fused mix + inline dot) --------
__global__ void k_mol_edge(const int* __restrict__ batch, const float* __restrict__ xv,
                           const float* __restrict__ mixb,
                           const float* __restrict__ gdot, const float* __restrict__ ndot,
                           const float* __restrict__ ajw, const float* __restrict__ bptr,
                           float* __restrict__ accG, float* __restrict__ denG)
{
    float b = __ldg(bptr);
    int tx = threadIdx.x, lane = tx & 31;
    int sub = lane >> 4, l4 = lane & 15;
    float4 aj4 = make_float4(0.f, 0.f, 0.f, 0.f);
    if (ajw) aj4 = *(const float4*)(ajw + l4*4);
    int wid = (blockIdx.x*blockDim.x + tx) >> 5;
    int nw  = (gridDim.x*blockDim.x) >> 5;
    for (int pair = wid; pair < NN/2; pair += nw){
        int n = pair*2 + sub;
        int g = batch[n];
        float4 m = *(const float4*)(xv + n*64 + l4*4);
        float nd;
        if (mixb){
            float4 w = *(const float4*)(mixb + n*64 + l4*4);
            m.x = 0.5f*(m.x + w.x); m.y = 0.5f*(m.y + w.y);
            m.z = 0.5f*(m.z + w.z); m.w = 0.5f*(m.w + w.w);
            nd = m.x*aj4.x + m.y*aj4.y + m.z*aj4.z + m.w*aj4.w;
            #pragma unroll
            for (int o = 8; o > 0; o >>= 1) nd += __shfl_xor_sync(0xffffffffu, nd, o);
        } else {
            nd = __ldg(ndot + n);
        }
        float ec = expf(leaky(gdot[g] + nd + b));
        red4(accG + g*64 + l4*4, ec*m.x, ec*m.y, ec*m.z, ec*m.w);
        if (l4 == 0) atomicAdd(denG + g, ec);
    }
}

// ---------------- per-row dot, optional in-place relu ----------------
__global__ void k_dotg(float* __restrict__ o1, const float* __restrict__ w1,
                       float* __restrict__ in, int nrows, int dorelu)
{
    int wid  = (blockIdx.x*blockDim.x + threadIdx.x) >> 5;
    int lane = threadIdx.x & 31;
    int nw   = (gridDim.x*blockDim.x) >> 5;
    for (int r = wid; r < nrows; r += nw){
        float v1 = in[r*64 + lane], v2 = in[r*64 + lane + 32];
        if (dorelu){
            v1 = fmaxf(v1, 0.f); v2 = fmaxf(v2, 0.f);
            in[r*64 + lane] = v1; in[r*64 + lane + 32] = v2;
        }
        float s = v1*__ldg(w1+lane) + v2*__ldg(w1+lane+32);
        #pragma unroll
        for (int o = 16; o > 0; o >>= 1) s += __shfl_xor_sync(0xffffffffu, s, o);
        if (lane == 0) o1[r] = s;
    }
}

__global__ void k_final(const float* __restrict__ gout, const float* __restrict__ w,
                        const float* __restrict__ b, float* __restrict__ out, int n)
{
    int wid  = (blockIdx.x*blockDim.x + threadIdx.x) >> 5;
    int lane = threadIdx.x & 31;
    if (wid >= n) return;
    float s = gout[wid*64 + lane]*__ldg(w + lane) + gout[wid*64 + lane + 32]*__ldg(w + lane + 32);
    #pragma unroll
    for (int o = 16; o > 0; o >>= 1) s += __shfl_xor_sync(0xffffffffu, s, o);
    if (lane == 0) out[wid] = s + __ldg(b);
}

// =====================================================================
extern "C" void kernel_launch(void* const* d_in, const int* in_sizes, int n_in,
                              void* d_out_, int out_size)
{
    const float* raw           = (const float*)d_in[0];
    const int*   ei            = (const int*)  d_in[1];
    const float* eattr         = (const float*)d_in[2];
    const int*   batch         = (const int*)  d_in[3];
    const float* lin1_w        = (const float*)d_in[4];
    const float* lin1_b        = (const float*)d_in[5];
    const float* gate_nl_w     = (const float*)d_in[6];
    const float* gate_nl_b     = (const float*)d_in[7];
    const float* gate_align_w  = (const float*)d_in[8];
    const float* gate_align_b  = (const float*)d_in[9];
    const float* gate_attend_w = (const float*)d_in[10];
    const float* gate_attend_b = (const float*)d_in[11];
    const float* conv_align_w  = (const float*)d_in[12];
    const float* conv_align_b  = (const float*)d_in[13];
    const float* conv_attend_w = (const float*)d_in[14];
    const float* conv_attend_b = (const float*)d_in[15];
    const float* agru_wih      = (const float*)d_in[16];
    const float* agru_whh      = (const float*)d_in[17];
    const float* agru_bih      = (const float*)d_in[18];
    const float* agru_bhh      = (const float*)d_in[19];
    const float* mol_align_w   = (const float*)d_in[20];
    const float* mol_align_b   = (const float*)d_in[21];
    const float* mol_attend_w  = (const float*)d_in[22];
    const float* mol_attend_b  = (const float*)d_in[23];
    const float* mgru_wih      = (const float*)d_in[24];
    const float* mgru_whh      = (const float*)d_in[25];
    const float* mgru_bih      = (const float*)d_in[26];
    const float* mgru_bhh      = (const float*)d_in[27];
    const float* lin2_w        = (const float*)d_in[28];
    const float* lin2_b        = (const float*)d_in[29];
    float* outp = (float*)d_out_;

    float *px, *pxl1, *ph, *pp, *pdots, *ppan2, *paccd, *pgout, *pmol, *pgdot;
    cudaGetSymbolAddress((void**)&px,     g_x);
    cudaGetSymbolAddress((void**)&pxl1,   g_xl1);
    cudaGetSymbolAddress((void**)&ph,     g_h);
    cudaGetSymbolAddress((void**)&pp,     g_p);
    cudaGetSymbolAddress((void**)&pdots,  g_dots);
    cudaGetSymbolAddress((void**)&ppan2,  g_pan2);
    cudaGetSymbolAddress((void**)&paccd,  g_accd);
    cudaGetSymbolAddress((void**)&pgout,  g_gout);
    cudaGetSymbolAddress((void**)&pmol,   g_molaccd);
    cudaGetSymbolAddress((void**)&pgdot,  g_gdot);

    float* pai    = pdots;
    float* pan    = pdots + NN;
    float* pacc   = paccd;
    float* pdenom = paccd + NN*64;
    float* paccG  = pmol;
    float* pdenG  = pmol + GG*64;
    uint2* phu = (uint2*)ph;
    uint2* ppu = (uint2*)pp;

    const int GRU_SMEM  = (4*32*BLDH + 4*64*AHLD) * 4 + 1024;  // 91136
    const int PROJ_SMEM = (4*32*MB + 2*64*AHLD) * 4;
    const int ATT_SMEM  = (2*32*MB + 2*64*AHLD) * 4 + 256;
    cudaFuncSetAttribute(k_gru,  cudaFuncAttributeMaxDynamicSharedMemorySize, GRU_SMEM);
    cudaFuncSetAttribute(k_proj, cudaFuncAttributeMaxDynamicSharedMemorySize, PROJ_SMEM);
    cudaFuncSetAttribute(k_att,  cudaFuncAttributeMaxDynamicSharedMemorySize, ATT_SMEM);

    const int NT = (NN + 63) / 64;
    const int GT = (GG + 63) / 64;
    const int PG  = NT < 592 ? NT : 592;
    const int AG  = NT < 592 ? NT : 592;
    const int GRG  = 296;
    const int GRGG = 2*GT < 296 ? 2*GT : 296;

    // ---- initial zeroing ----
    cudaMemsetAsync(pdots, 0, 2*NN*sizeof(float));
    cudaMemsetAsync(paccd, 0, (NN*64 + NN)*sizeof(float));
    cudaMemsetAsync(pgout, 0, GG*64*sizeof(float));
    cudaMemsetAsync(pmol,  0, (GG*64 + GG)*sizeof(float));

    // ---- dual projection ----
    k_proj<<<PG, 256, PROJ_SMEM>>>(px, pp, raw, lin1_w, lin1_b, gate_nl_w, gate_nl_b,
                                   gate_align_w, pai, NN);

    // ---- GATEConv ----
    k_gate_edge<<<2048, 256>>>(ei, eattr, pp, pai, gate_nl_w, gate_align_w, gate_align_b,
                               pacc, pdenom);
    k_att<<<AG, 256, ATT_SMEM>>>(phu, pacc, pdenom, gate_attend_w, gate_attend_b,
                                 pai, pan, NN);
    k_gru<<<GRG, 256, GRU_SMEM>>>(px, nullptr, phu, px,
                                  agru_wih, agru_whh, agru_bih, agru_bhh,
                                  conv_align_w, conv_align_w + 64, pai, pan,
                                  nullptr, nullptr, NN);

    // ---- GATConv l = 0 ----
    k_conv_edge<<<2048, 256>>>(ei, px, pai, pan, conv_align_b, pacc, pdenom);
    k_att<<<AG, 256, ATT_SMEM>>>(phu, pacc, pdenom, conv_attend_w, conv_attend_b,
                                 pai, pan, NN);
    k_gru<<<GRG, 256, GRU_SMEM>>>(px, pxl1, phu, px,
                                  agru_wih + 192*64, agru_whh + 192*64,
                                  agru_bih + 192,    agru_bhh + 192,
                                  conv_align_w + 128, conv_align_w + 192, pai, pan,
                                  nullptr, nullptr, NN);

    // ---- GATConv l = 1 ----
    k_conv_edge<<<2048, 256>>>(ei, px, pai, pan, conv_align_b + 1, pacc, pdenom);
    k_att<<<AG, 256, ATT_SMEM>>>(phu, pacc, pdenom, conv_attend_w + 4096, conv_attend_b + 64,
                                 ppan2, nullptr, NN);
    k_gru<<<GRG, 256, GRU_SMEM>>>(px, nullptr, phu, px,
                                  agru_wih + 2*192*64, agru_whh + 2*192*64,
                                  agru_bih + 2*192,    agru_bhh + 2*192,
                                  mol_align_w + 64, nullptr, ppan2, nullptr,
                                  batch, pgout, NN);

    // ---- molecule readout ----
    k_dotg<<<128, 256>>>(pgdot, mol_align_w, pgout, GG, 1);

    // t = 0: mixed = 0.5*(x + xl1), fused in mol_edge
    k_mol_edge<<<512, 256>>>(batch, px, pxl1, pgdot, nullptr,
                             mol_align_w + 64, mol_align_b, paccG, pdenG);
    k_att<<<GT, 256, ATT_SMEM>>>(ppu, paccG, pdenG, mol_attend_w, mol_attend_b,
                                 nullptr, nullptr, GG);
    k_gru<<<GRGG, 256, GRU_SMEM>>>(pgout, nullptr, ppu, pgout,
                                   mgru_wih, mgru_whh, mgru_bih, mgru_bhh,
                                   nullptr, nullptr, nullptr, nullptr,
                                   nullptr, nullptr, GG);

    // t = 1: mixed == x; ndot = ppan2
    k_dotg<<<128, 256>>>(pgdot, mol_align_w, pgout, GG, 0);
    k_mol_edge<<<512, 256>>>(batch, px, nullptr, pgdot, ppan2,
                             nullptr, mol_align_b, paccG, pdenG);
    k_att<<<GT, 256, ATT_SMEM>>>(ppu, paccG, pdenG, mol_attend_w, mol_attend_b,
                                 nullptr, nullptr, GG);
    k_gru<<<GRGG, 256, GRU_SMEM>>>(pgout, nullptr, ppu, pgout,
                                   mgru_wih, mgru_whh, mgru_bih, mgru_bhh,
                                   nullptr, nullptr, nullptr, nullptr,
                                   nullptr, nullptr, GG);

    k_final<<<(GG*32 + 255)/256, 256>>>(pgout, lin2_w, lin2_b, outp, GG);
}